// round 10
// baseline (speedup 1.0000x reference)
#include <cuda_runtime.h>

typedef unsigned long long u64;

#define LOG2E 1.4426950408889634f
#define LN2   0.6931471805599453f
#define B    512
#define TT   1024
#define L    48
#define RING 16   // cp.async emission ring slots (512B each)

__device__ float g_fwd[B];
__device__ float g_gold[B];

static __device__ __forceinline__ u64 pk2(float lo, float hi){ u64 r; asm("mov.b64 %0, {%1, %2};" : "=l"(r) : "f"(lo), "f"(hi)); return r; }
static __device__ __forceinline__ void upk2(u64 v, float& lo, float& hi){ asm("mov.b64 {%0, %1}, %2;" : "=f"(lo), "=f"(hi) : "l"(v)); }
static __device__ __forceinline__ u64 fma2(u64 a, u64 b, u64 c){ u64 d; asm("fma.rn.f32x2 %0, %1, %2, %3;" : "=l"(d) : "l"(a), "l"(b), "l"(c)); return d; }
static __device__ __forceinline__ u64 add2(u64 a, u64 b){ u64 d; asm("add.rn.f32x2 %0, %1, %2;" : "=l"(d) : "l"(a), "l"(b)); return d; }
static __device__ __forceinline__ float ex2f(float x){ float y; asm("ex2.approx.ftz.f32 %0, %1;" : "=f"(y) : "f"(x)); return y; }
static __device__ __forceinline__ float lg2f(float x){ float y; asm("lg2.approx.ftz.f32 %0, %1;" : "=f"(y) : "f"(x)); return y; }
static __device__ __forceinline__ unsigned smem_u32(const void* p){
    unsigned a; asm("{ .reg .u64 t; cvta.to.shared.u64 t, %1; cvt.u32.u64 %0, t; }" : "=r"(a) : "l"(p)); return a; }

// ---------------------------------------------------------------------------
// Forward kernel: 256 blocks x 96 threads (3 warps), 2 sequences per block.
// Thread (seq = tid/48, j = tid%48) computes label j's dot with INPUT-PAIR
// f32x2 packing: multiplier (u_i, u_{i+1}) comes directly from the plain
// state layout via LDS.128; et is 24 packed u64 (48 regs, no spill).
// 24 FMA2 replaces 48 FFMA -> ~33% fewer warp-instrs/step than R8.
// Loop structure identical to R8 (per-step wait_group 14, unroll 1).
// ---------------------------------------------------------------------------
__global__ __launch_bounds__(96, 1) void crf_fwd_kernel(
    const float* __restrict__ em, const int* __restrict__ mask,
    const float* __restrict__ trans, const float* __restrict__ startt,
    const float* __restrict__ endt)
{
    __shared__ __align__(16) float sh_u[2][96];        // [0..47]=A, [48..95]=B
    __shared__ __align__(16) float sh_em[RING][128];   // ring: [0..47]=A, [64..111]=B
    __shared__ unsigned mb[2][32];                     // mask bits per seq
    __shared__ float sc[96];

    const int tid = threadIdx.x;
    const int seq = tid >= 48;            // 0 = A, 1 = B
    const int j   = tid - seq * 48;
    const int bA  = blockIdx.x * 2;
    const int bme = bA + seq;             // this thread's batch element

    // ---- mask bits via ballot (warp 0 does both sequences) ----
    if (tid < 32) {
        #pragma unroll 1
        for (int k = 0; k < 32; k++) {
            int vA = mask[bA * TT + k * 32 + tid];
            unsigned wA = __ballot_sync(0xFFFFFFFFu, vA != 0);
            if (tid == k) mb[0][k] = wA;
            int vB = mask[(bA + 1) * TT + k * 32 + tid];
            unsigned wB = __ballot_sync(0xFFFFFFFFu, vB != 0);
            if (tid == k) mb[1][k] = wB;
        }
    }

    // ---- transition column j, exponentiated, input-pair packed (24 u64) ----
    u64 et2[L / 2];
    #pragma unroll
    for (int q = 0; q < L / 2; q++) {
        float e0 = ex2f(trans[(2 * q)     * L + j] * LOG2E);
        float e1 = ex2f(trans[(2 * q + 1) * L + j] * LOG2E);
        et2[q] = pk2(e0, e1);
    }
    const float expEnd = ex2f(endt[j] * LOG2E);

    // ---- initial state u0 = exp(start + em[0]) ----
    float res = ex2f((startt[j] + em[(size_t)bme * TT * L + j]) * LOG2E);
    sh_u[0][seq * 48 + j] = res;

    // ---- cp.async producer: lanes 0..11 -> seq A, 12..23 -> seq B ----
    const float* gbase = (tid < 12) ? (em + (size_t)bA * TT * L + tid * 4)
                                    : (em + (size_t)(bA + 1) * TT * L + (tid - 12) * 4);
    const unsigned dst_off  = (tid < 12) ? (unsigned)(tid * 16) : (unsigned)(256 + (tid - 12) * 16);
    const unsigned ring_base = smem_u32(&sh_em[0][0]);

    for (int tp = 1; tp < RING; ++tp) {
        if (tid < 24) {
            const float* src = gbase + (size_t)tp * L;
            unsigned d = ring_base + (unsigned)tp * 512u + dst_off;
            asm volatile("cp.async.cg.shared.global [%0], [%1], 16;" :: "r"(d), "l"(src));
        }
        asm volatile("cp.async.commit_group;");
    }
    asm volatile("cp.async.wait_group 14;");   // row 1 resident
    __syncthreads();

    int iA = 0;                                // exact integer log2 credit
    const float* pr = &sh_u[0][seq * 48];
    float*       pw = &sh_u[1][seq * 48];

    #pragma unroll 1
    for (int t = 1; t < TT; ++t) {
        // ---- 48-MAC dot as 24 FMA2 over input pairs (12 LDS.128) ----
        const ulonglong2* up = reinterpret_cast<const ulonglong2*>(pr);
        u64 a0 = 0, a1 = 0, a2 = 0, a3 = 0;
        u64 first2 = 0;
        #pragma unroll
        for (int q = 0; q < 6; q++) {
            ulonglong2 v = up[2 * q];          // (u_{8q},u_{8q+1}) , (u_{8q+2},u_{8q+3})
            ulonglong2 w = up[2 * q + 1];      // (u_{8q+4},u_{8q+5}) , (u_{8q+6},u_{8q+7})
            if (q == 0) first2 = v.x;          // (u0, u1) — lo half is renorm ref
            a0 = fma2(v.x, et2[4 * q + 0], a0);
            a1 = fma2(v.y, et2[4 * q + 1], a1);
            a2 = fma2(w.x, et2[4 * q + 2], a2);
            a3 = fma2(w.y, et2[4 * q + 3], a3);
        }
        u64 d2 = add2(add2(a0, a1), add2(a2, a3));
        float dlo, dhi; upk2(d2, dlo, dhi);
        float dot = dlo + dhi;

        // ---- emission + mask bit ----
        const int slot = t & (RING - 1);
        float Ee = ex2f(sh_em[slot][seq * 64 + j] * LOG2E);
        float prod = dot * Ee;
        bool mbit = (mb[seq][t >> 5] >> (t & 31)) & 1u;
        float sel = mbit ? prod : res;

        if ((t & 3) == 0) {                    // exact power-of-2 renorm (from u[0])
            float f0, f1; upk2(first2, f0, f1);
            unsigned eb = __float_as_uint(f0) & 0x7F800000u;
            sel *= __uint_as_float(0x7F000000u - eb);
            iA += (int)(eb >> 23) - 127;
        }
        res = sel;
        pw[j] = res;

        // ---- refill ring slot for row t+15 (clamped) ----
        {
            int tf = t + (RING - 1); if (tf > TT - 1) tf = TT - 1;
            if (tid < 24) {
                const float* src = gbase + (size_t)tf * L;
                unsigned d = ring_base + (unsigned)(tf & (RING - 1)) * 512u + dst_off;
                asm volatile("cp.async.cg.shared.global [%0], [%1], 16;" :: "r"(d), "l"(src));
            }
            asm volatile("cp.async.commit_group;");
            asm volatile("cp.async.wait_group 14;");   // row t+1 resident
        }

        float* tmp = (float*)pr; pr = pw; pw = tmp;
        __syncthreads();
    }

    // ---- finalize: logZ = (log2(sum_j u_j * exp(end_j)) + credit) * ln2 ----
    sc[tid] = res * expEnd;
    __syncthreads();
    if (j == 0) {                              // tid 0 (seq A) and tid 48 (seq B)
        float s = 0.f;
        #pragma unroll
        for (int q = 0; q < L; q++) s += sc[seq * 48 + q];
        g_fwd[bme] = (lg2f(s) + (float)iA) * LN2;
    }
}

// ---------------------------------------------------------------------------
// Gold score kernel: one block per batch element.
// ---------------------------------------------------------------------------
__global__ __launch_bounds__(256, 4) void crf_gold_kernel(
    const float* __restrict__ em, const int* __restrict__ labels,
    const int* __restrict__ mask, const float* __restrict__ trans,
    const float* __restrict__ startt, const float* __restrict__ endt)
{
    __shared__ float red[256];
    __shared__ int   redc[256];
    const int b = blockIdx.x;
    const int tid = threadIdx.x;

    float acc = 0.f;
    int cnt = 0;
    for (int t = tid; t < TT; t += 256) {
        int l = labels[b * TT + t];
        int m = mask[b * TT + t];
        cnt += m;
        float e = em[((size_t)(b * TT) + t) * L + l];
        if (t == 0) {
            acc += startt[l] + e;
        } else {
            int lp = labels[b * TT + t - 1];
            acc += (e + trans[l * L + lp]) * (float)m;
        }
    }
    red[tid] = acc; redc[tid] = cnt;
    __syncthreads();
    for (int s = 128; s > 0; s >>= 1) {
        if (tid < s) { red[tid] += red[tid + s]; redc[tid] += redc[tid + s]; }
        __syncthreads();
    }
    if (tid == 0) {
        int len = redc[0] - 1;
        int last = labels[b * TT + len];
        g_gold[b] = red[0] + endt[last];
    }
}

// ---------------------------------------------------------------------------
// Final reduction: mean(fwd - gold)
// ---------------------------------------------------------------------------
__global__ __launch_bounds__(512, 1) void crf_final_kernel(float* __restrict__ out)
{
    __shared__ float red[512];
    int tid = threadIdx.x;
    red[tid] = g_fwd[tid] - g_gold[tid];
    __syncthreads();
    for (int s = 256; s > 0; s >>= 1) {
        if (tid < s) red[tid] += red[tid + s];
        __syncthreads();
    }
    if (tid == 0) out[0] = red[0] * (1.0f / (float)B);
}

extern "C" void kernel_launch(void* const* d_in, const int* in_sizes, int n_in,
                              void* d_out, int out_size)
{
    const float* em     = (const float*)d_in[0];
    const int*   labels = (const int*)  d_in[1];
    const int*   mask   = (const int*)  d_in[2];
    const float* trans  = (const float*)d_in[3];
    const float* startt = (const float*)d_in[4];
    const float* endt   = (const float*)d_in[5];
    float* out = (float*)d_out;

    crf_fwd_kernel<<<B / 2, 96>>>(em, mask, trans, startt, endt);
    crf_gold_kernel<<<B, 256>>>(em, labels, mask, trans, startt, endt);
    crf_final_kernel<<<1, 512>>>(out);
}

// round 11
// speedup vs baseline: 1.5352x; 1.5352x over previous
#include <cuda_runtime.h>

#define LOG2E 1.4426950408889634f
#define LN2   0.6931471805599453f
#define B    512
#define TT   1024
#define L    48
#define RING 16   // cp.async emission ring slots (192B each)

__device__ float g_fwd[B];
__device__ float g_gold[B];

static __device__ __forceinline__ float ex2f(float x){ float y; asm("ex2.approx.ftz.f32 %0, %1;" : "=f"(y) : "f"(x)); return y; }
static __device__ __forceinline__ float lg2f(float x){ float y; asm("lg2.approx.ftz.f32 %0, %1;" : "=f"(y) : "f"(x)); return y; }
static __device__ __forceinline__ unsigned smem_u32(const void* p){
    unsigned a; asm("{ .reg .u64 t; cvta.to.shared.u64 t, %1; cvt.u32.u64 %0, t; }" : "=r"(a) : "l"(p)); return a; }

// ---------------------------------------------------------------------------
// Forward kernel: 512 blocks x 64 threads (2 warps), ONE sequence per block.
// Same proven R8 step body (scalar 48-FMA dot, 8 accumulators, per-step
// wait_group, pow-2 renorm). Rationale: R8 was latency-bound at 1.3 warps
// per SMSP (issue 45.6%); halving block size doubles independent chains per
// scheduler so stalls of one chain are filled by the other.
// Thread j (jc = min(j,47)) owns label jc; shadow lanes duplicate label 47.
// ---------------------------------------------------------------------------
__global__ __launch_bounds__(64, 1) void crf_fwd_kernel(
    const float* __restrict__ em, const int* __restrict__ mask,
    const float* __restrict__ trans, const float* __restrict__ startt,
    const float* __restrict__ endt)
{
    __shared__ __align__(16) float sh_u[2][48];        // ping-pong state
    __shared__ __align__(16) float sh_em[RING][48];    // emission ring (3KB)
    __shared__ unsigned mb[32];                        // mask bits
    __shared__ float sc[48];

    const int j  = threadIdx.x;
    const int jc = j < L ? j : (L - 1);                // clamp shadow lanes
    const int b  = blockIdx.x;

    // ---- mask bits via ballot (warp 0) ----
    if (j < 32) {
        #pragma unroll 1
        for (int k = 0; k < 32; k++) {
            int v = mask[b * TT + k * 32 + j];
            unsigned w = __ballot_sync(0xFFFFFFFFu, v != 0);
            if (j == k) mb[k] = w;
        }
    }

    // ---- transition column jc, exponentiated, scalar (48 regs) ----
    float et[L];
    #pragma unroll
    for (int i = 0; i < L; i++)
        et[i] = ex2f(trans[i * L + jc] * LOG2E);
    const float expEnd = ex2f(endt[jc] * LOG2E);

    // ---- initial state u0 = exp(start + em[0]) ----
    float res = ex2f((startt[jc] + em[(size_t)b * TT * L + jc]) * LOG2E);
    sh_u[0][jc] = res;

    // ---- cp.async producer: lanes 0..11 copy 16B each (48 floats/row) ----
    const float* gbase = em + (size_t)b * TT * L + j * 4;
    const unsigned dst_off  = (unsigned)(j * 16);
    const unsigned ring_base = smem_u32(&sh_em[0][0]);

    for (int tp = 1; tp < RING; ++tp) {
        if (j < 12) {
            const float* src = gbase + (size_t)tp * L;
            unsigned d = ring_base + (unsigned)tp * 192u + dst_off;
            asm volatile("cp.async.cg.shared.global [%0], [%1], 16;" :: "r"(d), "l"(src));
        }
        asm volatile("cp.async.commit_group;");
    }
    asm volatile("cp.async.wait_group 14;");   // row 1 resident
    __syncthreads();

    int iA = 0;                                // exact integer log2 credit
    const float* pr = sh_u[0];
    float*       pw = sh_u[1];

    #pragma unroll 1
    for (int t = 1; t < TT; ++t) {
        // ---- scalar 48-FMA dot (12 broadcast LDS.128, 8 accumulators) ----
        const float4* up = reinterpret_cast<const float4*>(pr);
        float a0=0.f,a1=0.f,a2=0.f,a3=0.f,a4=0.f,a5=0.f,a6=0.f,a7=0.f;
        float first = 0.f;
        #pragma unroll
        for (int q = 0; q < 6; q++) {
            float4 v = up[2 * q];
            float4 w = up[2 * q + 1];
            if (q == 0) first = v.x;           // u[t-1][0] (renorm reference)
            a0 = fmaf(v.x, et[8 * q + 0], a0);
            a1 = fmaf(v.y, et[8 * q + 1], a1);
            a2 = fmaf(v.z, et[8 * q + 2], a2);
            a3 = fmaf(v.w, et[8 * q + 3], a3);
            a4 = fmaf(w.x, et[8 * q + 4], a4);
            a5 = fmaf(w.y, et[8 * q + 5], a5);
            a6 = fmaf(w.z, et[8 * q + 6], a6);
            a7 = fmaf(w.w, et[8 * q + 7], a7);
        }
        float dot = ((a0 + a1) + (a2 + a3)) + ((a4 + a5) + (a6 + a7));

        // ---- emission + mask bit ----
        const int slot = t & (RING - 1);
        float Ee = ex2f(sh_em[slot][jc] * LOG2E);
        float prod = dot * Ee;
        bool mbit = (mb[t >> 5] >> (t & 31)) & 1u;
        float sel = mbit ? prod : res;

        if ((t & 3) == 0) {                    // exact power-of-2 renorm
            unsigned eb = __float_as_uint(first) & 0x7F800000u;
            sel *= __uint_as_float(0x7F000000u - eb);
            iA += (int)(eb >> 23) - 127;
        }
        res = sel;
        pw[jc] = res;                          // shadows duplicate label 47 (same value)

        // ---- refill ring slot for row t+15 (clamped) ----
        {
            int tf = t + (RING - 1); if (tf > TT - 1) tf = TT - 1;
            if (j < 12) {
                const float* src = gbase + (size_t)tf * L;
                unsigned d = ring_base + (unsigned)(tf & (RING - 1)) * 192u + dst_off;
                asm volatile("cp.async.cg.shared.global [%0], [%1], 16;" :: "r"(d), "l"(src));
            }
            asm volatile("cp.async.commit_group;");
            asm volatile("cp.async.wait_group 14;");   // row t+1 resident
        }

        float* tmp = (float*)pr; pr = pw; pw = tmp;
        __syncthreads();
    }

    // ---- finalize: logZ = (log2(sum_j u_j * exp(end_j)) + credit) * ln2 ----
    if (j < L) sc[j] = res * expEnd;
    __syncthreads();
    if (j == 0) {
        float s = 0.f;
        #pragma unroll
        for (int q = 0; q < L; q++) s += sc[q];
        g_fwd[b] = (lg2f(s) + (float)iA) * LN2;
    }
}

// ---------------------------------------------------------------------------
// Gold score kernel: one block per batch element.
// ---------------------------------------------------------------------------
__global__ __launch_bounds__(256, 4) void crf_gold_kernel(
    const float* __restrict__ em, const int* __restrict__ labels,
    const int* __restrict__ mask, const float* __restrict__ trans,
    const float* __restrict__ startt, const float* __restrict__ endt)
{
    __shared__ float red[256];
    __shared__ int   redc[256];
    const int b = blockIdx.x;
    const int tid = threadIdx.x;

    float acc = 0.f;
    int cnt = 0;
    for (int t = tid; t < TT; t += 256) {
        int l = labels[b * TT + t];
        int m = mask[b * TT + t];
        cnt += m;
        float e = em[((size_t)(b * TT) + t) * L + l];
        if (t == 0) {
            acc += startt[l] + e;
        } else {
            int lp = labels[b * TT + t - 1];
            acc += (e + trans[l * L + lp]) * (float)m;
        }
    }
    red[tid] = acc; redc[tid] = cnt;
    __syncthreads();
    for (int s = 128; s > 0; s >>= 1) {
        if (tid < s) { red[tid] += red[tid + s]; redc[tid] += redc[tid + s]; }
        __syncthreads();
    }
    if (tid == 0) {
        int len = redc[0] - 1;
        int last = labels[b * TT + len];
        g_gold[b] = red[0] + endt[last];
    }
}

// ---------------------------------------------------------------------------
// Final reduction: mean(fwd - gold)
// ---------------------------------------------------------------------------
__global__ __launch_bounds__(512, 1) void crf_final_kernel(float* __restrict__ out)
{
    __shared__ float red[512];
    int tid = threadIdx.x;
    red[tid] = g_fwd[tid] - g_gold[tid];
    __syncthreads();
    for (int s = 256; s > 0; s >>= 1) {
        if (tid < s) red[tid] += red[tid + s];
        __syncthreads();
    }
    if (tid == 0) out[0] = red[0] * (1.0f / (float)B);
}

extern "C" void kernel_launch(void* const* d_in, const int* in_sizes, int n_in,
                              void* d_out, int out_size)
{
    const float* em     = (const float*)d_in[0];
    const int*   labels = (const int*)  d_in[1];
    const int*   mask   = (const int*)  d_in[2];
    const float* trans  = (const float*)d_in[3];
    const float* startt = (const float*)d_in[4];
    const float* endt   = (const float*)d_in[5];
    float* out = (float*)d_out;

    crf_fwd_kernel<<<B, 64>>>(em, mask, trans, startt, endt);
    crf_gold_kernel<<<B, 256>>>(em, labels, mask, trans, startt, endt);
    crf_final_kernel<<<1, 512>>>(out);
}

// round 12
// speedup vs baseline: 1.6546x; 1.0777x over previous
#include <cuda_runtime.h>

typedef unsigned long long u64;

#define LOG2E 1.4426950408889634f
#define LN2   0.6931471805599453f
#define B    512
#define TT   1024
#define L    48
#define RING 16   // cp.async emission ring slots (192B each)

__device__ float g_fwd[B];
__device__ float g_gold[B];

static __device__ __forceinline__ u64 pk2(float lo, float hi){ u64 r; asm("mov.b64 %0, {%1, %2};" : "=l"(r) : "f"(lo), "f"(hi)); return r; }
static __device__ __forceinline__ void upk2(u64 v, float& lo, float& hi){ asm("mov.b64 {%0, %1}, %2;" : "=f"(lo), "=f"(hi) : "l"(v)); }
static __device__ __forceinline__ u64 fma2(u64 a, u64 b, u64 c){ u64 d; asm("fma.rn.f32x2 %0, %1, %2, %3;" : "=l"(d) : "l"(a), "l"(b), "l"(c)); return d; }
static __device__ __forceinline__ u64 mul2(u64 a, u64 b){ u64 d; asm("mul.rn.f32x2 %0, %1, %2;" : "=l"(d) : "l"(a), "l"(b)); return d; }
static __device__ __forceinline__ u64 add2(u64 a, u64 b){ u64 d; asm("add.rn.f32x2 %0, %1, %2;" : "=l"(d) : "l"(a), "l"(b)); return d; }
static __device__ __forceinline__ float ex2f(float x){ float y; asm("ex2.approx.ftz.f32 %0, %1;" : "=f"(y) : "f"(x)); return y; }
static __device__ __forceinline__ float lg2f(float x){ float y; asm("lg2.approx.ftz.f32 %0, %1;" : "=f"(y) : "f"(x)); return y; }
static __device__ __forceinline__ unsigned smem_u32(const void* p){
    unsigned a; asm("{ .reg .u64 t; cvta.to.shared.u64 t, %1; cvt.u32.u64 %0, t; }" : "=r"(a) : "l"(p)); return a; }

// ---------------------------------------------------------------------------
// Forward kernel: 512 blocks x 32 threads — ONE warp per sequence, no block
// barriers (syncwarp only). This is the R6 architecture with the R7 register
// fix: __launch_bounds__(32, 1) lifts the reg ceiling to 255 so the packed
// et2[48] (96 regs) stays resident (R6 spilled at regs=126 -> 321us).
// Lane i (i<24) owns labels (2i, 2i+1) in f32x2. State exchanged via a
// duplicated smem layout (u,u,u+1,u+1): one STS.128/lane, consumer LDS.128
// yields pre-splatted FMA2 operands (packing cost paid by layout, not ALU).
// Emissions: 16-slot cp.async ring (15-step lookahead). Mask: 1 bit/step.
// Renorm: exact power-of-2 from exponent(u[0]) every 4 steps.
// ---------------------------------------------------------------------------
__global__ __launch_bounds__(32, 1) void crf_fwd_kernel(
    const float* __restrict__ em, const int* __restrict__ mask,
    const float* __restrict__ trans, const float* __restrict__ startt,
    const float* __restrict__ endt)
{
    __shared__ __align__(16) float udup[2][128];      // dup state ping-pong
    __shared__ __align__(16) float ring[RING * 48];   // emission ring (3KB)
    __shared__ unsigned mb[32];                       // mask bits (1024 steps)

    const int lane = threadIdx.x;
    const int i  = lane < 24 ? lane : 23;             // clamp shadow lanes
    const int b  = blockIdx.x;
    const int j0 = 2 * i, j1 = 2 * i + 1;

    // ---- mask bits via ballot ----
    #pragma unroll 1
    for (int k = 0; k < 32; k++) {
        int v = mask[b * TT + k * 32 + lane];
        unsigned w = __ballot_sync(0xFFFFFFFFu, v != 0);
        if (lane == k) mb[k] = w;
    }

    // ---- transition columns (j0, j1), exponentiated, packed (48 u64) ----
    u64 et[L];
    #pragma unroll
    for (int k = 0; k < L; k++) {
        float e0 = ex2f(trans[k * L + j0] * LOG2E);
        float e1 = ex2f(trans[k * L + j1] * LOG2E);
        et[k] = pk2(e0, e1);
    }
    const float eEnd0 = ex2f(endt[j0] * LOG2E);
    const float eEnd1 = ex2f(endt[j1] * LOG2E);

    // ---- initial state u0 = exp(start + em[0]) ----
    u64 res;
    {
        float a = ex2f((startt[j0] + em[(size_t)b * TT * L + j0]) * LOG2E);
        float c = ex2f((startt[j1] + em[(size_t)b * TT * L + j1]) * LOG2E);
        res = pk2(a, c);
        float lo, hi; upk2(res, lo, hi);
        reinterpret_cast<float4*>(&udup[0][0])[lane] = make_float4(lo, lo, hi, hi);
    }

    // ---- cp.async ring prologue: lanes 0..11 copy 16B each (48 floats/row) ----
    const float* gsrc = em + (size_t)b * TT * L + lane * 4;
    const unsigned ring_base = smem_u32(&ring[0]);
    const unsigned dst_off = (unsigned)(lane * 16);
    for (int tp = 1; tp < RING; ++tp) {
        if (lane < 12) {
            const float* src = gsrc + (size_t)tp * L;
            unsigned d = ring_base + (unsigned)tp * 192u + dst_off;
            asm volatile("cp.async.cg.shared.global [%0], [%1], 16;" :: "r"(d), "l"(src));
        }
        asm volatile("cp.async.commit_group;");
    }
    asm volatile("cp.async.wait_group 14;");
    __syncwarp();

    int iA = 0;   // exact integer log2 credit
    const ulonglong2* rd = reinterpret_cast<const ulonglong2*>(&udup[0][0]);
    float4*           wr = reinterpret_cast<float4*>(&udup[1][0]);

    #pragma unroll 1
    for (int t = 1; t < TT; ++t) {
        // ---- 48x48 matvec: 24 broadcast LDS.128, 48 FMA2 into 4 accums ----
        u64 a0 = 0, a1 = 0, a2 = 0, a3 = 0;
        u64 first = 0;
        #pragma unroll
        for (int q = 0; q < 12; q++) {
            ulonglong2 wA = rd[2 * q];        // (splat u_{4q},   splat u_{4q+1})
            ulonglong2 wB = rd[2 * q + 1];    // (splat u_{4q+2}, splat u_{4q+3})
            if (q == 0) first = wA.x;
            a0 = fma2(wA.x, et[4 * q + 0], a0);
            a1 = fma2(wA.y, et[4 * q + 1], a1);
            a2 = fma2(wB.x, et[4 * q + 2], a2);
            a3 = fma2(wB.y, et[4 * q + 3], a3);
        }
        u64 dot = add2(add2(a0, a1), add2(a2, a3));

        // ---- emissions from ring + uniform mask bit ----
        const int slot = t & (RING - 1);
        u64 emp = *reinterpret_cast<const u64*>(&ring[slot * 48 + j0]);
        float emLo, emHi; upk2(emp, emLo, emHi);
        u64 Ee   = pk2(ex2f(emLo * LOG2E), ex2f(emHi * LOG2E));
        u64 prod = mul2(dot, Ee);
        bool mbit = (mb[t >> 5] >> (t & 31)) & 1u;
        u64 sel = mbit ? prod : res;

        if ((t & 3) == 0) {                   // exact power-of-2 renorm (from u[0])
            unsigned eb = (unsigned)first & 0x7F800000u;
            float f = __uint_as_float(0x7F000000u - eb);
            sel = mul2(sel, pk2(f, f));
            iA += (int)(eb >> 23) - 127;
        }
        res = sel;

        // ---- publish new state (dup layout, one STS.128) ----
        float lo, hi; upk2(res, lo, hi);
        wr[lane] = make_float4(lo, lo, hi, hi);

        // ---- refill ring slot for row t+15 (clamped) ----
        {
            int tf = t + (RING - 1); if (tf > TT - 1) tf = TT - 1;
            if (lane < 12) {
                const float* src = gsrc + (size_t)tf * L;
                unsigned d = ring_base + (unsigned)(tf & (RING - 1)) * 192u + dst_off;
                asm volatile("cp.async.cg.shared.global [%0], [%1], 16;" :: "r"(d), "l"(src));
            }
            asm volatile("cp.async.commit_group;");
            asm volatile("cp.async.wait_group 14;");
        }

        // swap ping-pong
        float4* nw = (float4*)rd;
        rd = (const ulonglong2*)wr;
        wr = nw;

        __syncwarp();
    }

    // ---- finalize: logZ = (log2(sum_j u_j * expEnd_j) + credit) * ln2 ----
    float lo, hi; upk2(res, lo, hi);
    float s = (lane < 24) ? (lo * eEnd0 + hi * eEnd1) : 0.f;
    #pragma unroll
    for (int o = 16; o > 0; o >>= 1) s += __shfl_down_sync(0xFFFFFFFFu, s, o);
    if (lane == 0) g_fwd[b] = (lg2f(s) + (float)iA) * LN2;
}

// ---------------------------------------------------------------------------
// Gold score kernel: one block per batch element.
// ---------------------------------------------------------------------------
__global__ __launch_bounds__(256, 4) void crf_gold_kernel(
    const float* __restrict__ em, const int* __restrict__ labels,
    const int* __restrict__ mask, const float* __restrict__ trans,
    const float* __restrict__ startt, const float* __restrict__ endt)
{
    __shared__ float red[256];
    __shared__ int   redc[256];
    const int b = blockIdx.x;
    const int tid = threadIdx.x;

    float acc = 0.f;
    int cnt = 0;
    for (int t = tid; t < TT; t += 256) {
        int l = labels[b * TT + t];
        int m = mask[b * TT + t];
        cnt += m;
        float e = em[((size_t)(b * TT) + t) * L + l];
        if (t == 0) {
            acc += startt[l] + e;
        } else {
            int lp = labels[b * TT + t - 1];
            acc += (e + trans[l * L + lp]) * (float)m;
        }
    }
    red[tid] = acc; redc[tid] = cnt;
    __syncthreads();
    for (int s = 128; s > 0; s >>= 1) {
        if (tid < s) { red[tid] += red[tid + s]; redc[tid] += redc[tid + s]; }
        __syncthreads();
    }
    if (tid == 0) {
        int len = redc[0] - 1;
        int last = labels[b * TT + len];
        g_gold[b] = red[0] + endt[last];
    }
}

// ---------------------------------------------------------------------------
// Final reduction: mean(fwd - gold)
// ---------------------------------------------------------------------------
__global__ __launch_bounds__(512, 1) void crf_final_kernel(float* __restrict__ out)
{
    __shared__ float red[512];
    int tid = threadIdx.x;
    red[tid] = g_fwd[tid] - g_gold[tid];
    __syncthreads();
    for (int s = 256; s > 0; s >>= 1) {
        if (tid < s) red[tid] += red[tid + s];
        __syncthreads();
    }
    if (tid == 0) out[0] = red[0] * (1.0f / (float)B);
}

extern "C" void kernel_launch(void* const* d_in, const int* in_sizes, int n_in,
                              void* d_out, int out_size)
{
    const float* em     = (const float*)d_in[0];
    const int*   labels = (const int*)  d_in[1];
    const int*   mask   = (const int*)  d_in[2];
    const float* trans  = (const float*)d_in[3];
    const float* startt = (const float*)d_in[4];
    const float* endt   = (const float*)d_in[5];
    float* out = (float*)d_out;

    crf_fwd_kernel<<<B, 32>>>(em, mask, trans, startt, endt);
    crf_gold_kernel<<<B, 256>>>(em, labels, mask, trans, startt, endt);
    crf_final_kernel<<<1, 512>>>(out);
}